// round 2
// baseline (speedup 1.0000x reference)
#include <cuda_runtime.h>
#include <math.h>
#include <stdint.h>

#define D   256
#define KC  100
#define BNEPS 1e-5f

// ------------------------- device scratch (no allocs allowed) -------------------------
__device__ float  g_h1[32768 * 256];     // hidden activations (reused for both MLPs)
__device__ float  g_p1[32768 * 256];     // p1 = proj MLP output
__device__ int    g_idx[32768];          // VQ code index per row
__device__ float  g_stats[1024];         // 2 banks x (colsum[256], colsumsq[256])
__device__ float  g_scale[512], g_shift[512];   // 2 banks of combined BN scale/shift
__device__ float  g_cnt[KC];             // code counts
__device__ float  g_embsq[KC];           // ||emb_k||^2
__device__ float  g_laU[KC * 6];         // emb @ latt_W + latt_b
__device__ float  g_hU[KC * D];          // unique-code hidden (invp MLP on emb rows)
__device__ float  g_outU[KC * D];        // unique-code invp output
__device__ float  g_scaleU[D], g_shiftU[D];
__device__ float  g_bsum[32768];         // per-graph ce sums
__device__ float  g_bcnt[32768];         // per-graph counts
__device__ double g_acc[8];              // 0 vq_sse, 1 loss_p, 2 loss_c, 3 loss_i, 5 latt

// ------------------------- helpers -------------------------
__device__ __forceinline__ float bred256(float v, float* red) {
    int t = threadIdx.x;
    red[t] = v;
    __syncthreads();
#pragma unroll
    for (int s = 128; s > 0; s >>= 1) {
        if (t < s) red[t] += red[t + s];
        __syncthreads();
    }
    float r = red[0];
    __syncthreads();
    return r;
}

// ------------------------- init -------------------------
__global__ void k_init() {
    int i = blockIdx.x * 256 + threadIdx.x;   // grid 128x256 -> 32768 threads
    g_bsum[i] = 0.f;
    g_bcnt[i] = 0.f;
    if (i < 1024) g_stats[i] = 0.f;
    if (i < KC)   g_cnt[i] = 0.f;
    if (i < 8)    g_acc[i] = 0.0;
}

// ------------------------- per-code precompute -------------------------
__global__ void k_emb_pre(const float* __restrict__ emb, const float* __restrict__ lw,
                          const float* __restrict__ lb) {
    __shared__ float red[256];
    int k = blockIdx.x, t = threadIdx.x;
    float v = emb[k * D + t];
    float s = bred256(v * v, red);
    if (t == 0) g_embsq[k] = s;
#pragma unroll
    for (int j = 0; j < 6; j++) {
        float s2 = bred256(v * lw[t * 6 + j], red);
        if (t == 0) g_laU[k * 6 + j] = s2 + lb[j];
    }
}

// ------------------------- VQ / atom GEMM (128 rows x 100 codes, K=256) -------------------------
// MODE 0: VQ on z2 -> argmin, counts, vq sse, lattice loss
// MODE 1: atom logits on zn -> log-softmax CE -> per-graph atomics
template <int MODE>
__global__ __launch_bounds__(256)
void k_cgemm(const float* __restrict__ A, const float* __restrict__ Bw,
             const float* __restrict__ bias, const int* __restrict__ tgt,
             const int* __restrict__ bidx,
             const float* __restrict__ ls, const float* __restrict__ smean,
             const float* __restrict__ sstd) {
    __shared__ float As[16 * 132];
    __shared__ float Bs[16 * 132];
    __shared__ float pv[128 * 17];
    __shared__ float pv2[128 * 17];
    __shared__ float rowsq[128 * 2];
    __shared__ float rr[128];
    __shared__ float red[256];

    const int tid = threadIdx.x;
    const int tx = tid & 15, ty = tid >> 4;
    const int m0 = blockIdx.x * 128;
    const int lm = tid >> 1;
    const int lk = (tid & 1) * 8;

    float acc[8][8];
#pragma unroll
    for (int i = 0; i < 8; i++)
#pragma unroll
        for (int j = 0; j < 8; j++) acc[i][j] = 0.f;
    float asq = 0.f;

    for (int k0 = 0; k0 < D; k0 += 16) {
        const float* Ap = A + (size_t)(m0 + lm) * D + k0 + lk;
        float4 a0 = *(const float4*)Ap;
        float4 a1 = *(const float4*)(Ap + 4);
        if (MODE == 0) {
            asq += a0.x * a0.x + a0.y * a0.y + a0.z * a0.z + a0.w * a0.w
                 + a1.x * a1.x + a1.y * a1.y + a1.z * a1.z + a1.w * a1.w;
        }
        As[(lk + 0) * 132 + lm] = a0.x; As[(lk + 1) * 132 + lm] = a0.y;
        As[(lk + 2) * 132 + lm] = a0.z; As[(lk + 3) * 132 + lm] = a0.w;
        As[(lk + 4) * 132 + lm] = a1.x; As[(lk + 5) * 132 + lm] = a1.y;
        As[(lk + 6) * 132 + lm] = a1.z; As[(lk + 7) * 132 + lm] = a1.w;

        if (MODE == 1) {
            int kk = tid >> 4, ns = (tid & 15) * 8;
#pragma unroll
            for (int e = 0; e < 8; e++) {
                int n = ns + e;
                Bs[kk * 132 + n] = (n < KC) ? Bw[(size_t)(k0 + kk) * KC + n] : 0.f;
            }
        } else {
#pragma unroll
            for (int i2 = tid; i2 < 2048; i2 += 256) {
                int n = i2 >> 4, kk = i2 & 15;
                Bs[kk * 132 + n] = (n < KC) ? Bw[(size_t)n * D + k0 + kk] : 0.f;
            }
        }
        __syncthreads();
#pragma unroll
        for (int kk = 0; kk < 16; kk++) {
            const float* ap = &As[kk * 132 + ty * 8];
            const float* bp = &Bs[kk * 132 + tx * 8];
            float4 A0 = *(const float4*)ap, A1 = *(const float4*)(ap + 4);
            float4 B0 = *(const float4*)bp, B1 = *(const float4*)(bp + 4);
            float av[8] = {A0.x, A0.y, A0.z, A0.w, A1.x, A1.y, A1.z, A1.w};
            float bv[8] = {B0.x, B0.y, B0.z, B0.w, B1.x, B1.y, B1.z, B1.w};
#pragma unroll
            for (int i = 0; i < 8; i++)
#pragma unroll
                for (int j = 0; j < 8; j++)
                    acc[i][j] = fmaf(av[i], bv[j], acc[i][j]);
        }
        __syncthreads();
    }

    if (MODE == 0) {
        rowsq[lm * 2 + (tid & 1)] = asq;
#pragma unroll
        for (int i = 0; i < 8; i++) {
            float bm = 3.4e38f;
            int ba = 0;
#pragma unroll
            for (int j = 0; j < 8; j++) {
                int col = tx * 8 + j;
                if (col < KC) {
                    float dd = g_embsq[col] - 2.f * acc[i][j];
                    if (dd < bm) { bm = dd; ba = col; }
                }
            }
            pv[(ty * 8 + i) * 17 + tx] = bm;
            pv2[(ty * 8 + i) * 17 + tx] = __int_as_float(ba);
        }
        __syncthreads();
        float myloc = 0.f, mylat = 0.f;
        if (tid < 128) {
            int row = tid;
            float bm = 3.4e38f;
            int ba = 0;
#pragma unroll
            for (int t2 = 0; t2 < 16; t2++) {
                float v = pv[row * 17 + t2];
                if (v < bm) { bm = v; ba = __float_as_int(pv2[row * 17 + t2]); }
            }
            int grow = m0 + row;
            g_idx[grow] = ba;
            atomicAdd(&g_cnt[ba], 1.f);
            myloc = bm + rowsq[row * 2] + rowsq[row * 2 + 1];
            float lat = 0.f;
#pragma unroll
            for (int j = 0; j < 6; j++) {
                float tv = (ls[(size_t)grow * 6 + j] - smean[j]) / sstd[j];
                float dd = g_laU[ba * 6 + j] - tv;
                lat += dd * dd;
            }
            mylat = lat;
        }
        float r1 = bred256(myloc, red);
        float r2 = bred256(mylat, red);
        if (tid == 0) {
            atomicAdd(&g_acc[0], (double)r1);
            atomicAdd(&g_acc[5], (double)r2);
        }
    } else {
        float bb[8];
#pragma unroll
        for (int j = 0; j < 8; j++) {
            int col = tx * 8 + j;
            bb[j] = (col < KC) ? bias[col] : 0.f;
        }
#pragma unroll
        for (int i = 0; i < 8; i++) {
            float bm = -3.4e38f;
#pragma unroll
            for (int j = 0; j < 8; j++) {
                int col = tx * 8 + j;
                if (col < KC) {
                    acc[i][j] += bb[j];
                    bm = fmaxf(bm, acc[i][j]);
                }
            }
            pv[(ty * 8 + i) * 17 + tx] = bm;
        }
        __syncthreads();
        if (tid < 128) {
            float m = -3.4e38f;
#pragma unroll
            for (int t2 = 0; t2 < 16; t2++) m = fmaxf(m, pv[tid * 17 + t2]);
            rr[tid] = m;
        }
        __syncthreads();
#pragma unroll
        for (int i = 0; i < 8; i++) {
            int row = ty * 8 + i;
            float m = rr[row];
            int tg = tgt[m0 + row];
            float s = 0.f, tl = 0.f;
#pragma unroll
            for (int j = 0; j < 8; j++) {
                int col = tx * 8 + j;
                if (col < KC) {
                    s += __expf(acc[i][j] - m);
                    if (col == tg) tl = acc[i][j];
                }
            }
            pv[row * 17 + tx] = s;
            pv2[row * 17 + tx] = tl;
        }
        __syncthreads();
        if (tid < 128) {
            float s = 0.f, tl = 0.f;
#pragma unroll
            for (int t2 = 0; t2 < 16; t2++) {
                s += pv[tid * 17 + t2];
                tl += pv2[tid * 17 + t2];
            }
            float ce = rr[tid] + __logf(s) - tl;
            int gb = bidx[m0 + tid];
            atomicAdd(&g_bsum[gb], ce);
            atomicAdd(&g_bcnt[gb], 1.f);
        }
    }
}

// ------------------------- D x D MLP GEMM (M=32768, N=256, K=256) -------------------------
// EPI 0: store C, accumulate column sum/sumsq into stats bank
// EPI 1: store C, accumulate sum((C - emb[g_idx[row]])^2) -> loss_p
// EPI 2: no store, accumulate sum((C - cmp[row])^2)       -> loss_c
// BN: apply relu(h*scale+shift) on A-tile load (scale/shift from bank)
template <int EPI, int BN>
__global__ __launch_bounds__(256)
void k_dgemm(const float* __restrict__ Aext, int aSel,
             const float* __restrict__ Bw, const float* __restrict__ bias,
             int outSel, int bank, const float* __restrict__ cmp) {
    __shared__ float As[16 * 132];
    __shared__ float Bs[16 * 132];
    __shared__ float sS[256], sH[256];
    __shared__ float red[256];
    __shared__ float scol[128], scol2[128];
    __shared__ int sidx[128];

    const int tid = threadIdx.x;
    const int tx = tid & 15, ty = tid >> 4;
    const int m0 = blockIdx.y * 128, n0 = blockIdx.x * 128;
    const int lm = tid >> 1;
    const int lk = (tid & 1) * 8;

    const float* A = (aSel == 0) ? Aext : ((aSel == 1) ? g_h1 : g_p1);
    float* Cp = (outSel == 1) ? g_h1 : g_p1;

    if (BN) {
        sS[tid] = g_scale[bank * 256 + tid];
        sH[tid] = g_shift[bank * 256 + tid];
    }
    if (EPI == 0 && tid < 128) { scol[tid] = 0.f; scol2[tid] = 0.f; }
    if (EPI == 1 && tid < 128) sidx[tid] = g_idx[m0 + tid];
    __syncthreads();

    float acc[8][8];
#pragma unroll
    for (int i = 0; i < 8; i++)
#pragma unroll
        for (int j = 0; j < 8; j++) acc[i][j] = 0.f;

    for (int k0 = 0; k0 < D; k0 += 16) {
        const float* Ap = A + (size_t)(m0 + lm) * D + k0 + lk;
        float4 a0 = *(const float4*)Ap;
        float4 a1 = *(const float4*)(Ap + 4);
        if (BN) {
            int c = k0 + lk;
            a0.x = fmaxf(0.f, fmaf(a0.x, sS[c + 0], sH[c + 0]));
            a0.y = fmaxf(0.f, fmaf(a0.y, sS[c + 1], sH[c + 1]));
            a0.z = fmaxf(0.f, fmaf(a0.z, sS[c + 2], sH[c + 2]));
            a0.w = fmaxf(0.f, fmaf(a0.w, sS[c + 3], sH[c + 3]));
            a1.x = fmaxf(0.f, fmaf(a1.x, sS[c + 4], sH[c + 4]));
            a1.y = fmaxf(0.f, fmaf(a1.y, sS[c + 5], sH[c + 5]));
            a1.z = fmaxf(0.f, fmaf(a1.z, sS[c + 6], sH[c + 6]));
            a1.w = fmaxf(0.f, fmaf(a1.w, sS[c + 7], sH[c + 7]));
        }
        As[(lk + 0) * 132 + lm] = a0.x; As[(lk + 1) * 132 + lm] = a0.y;
        As[(lk + 2) * 132 + lm] = a0.z; As[(lk + 3) * 132 + lm] = a0.w;
        As[(lk + 4) * 132 + lm] = a1.x; As[(lk + 5) * 132 + lm] = a1.y;
        As[(lk + 6) * 132 + lm] = a1.z; As[(lk + 7) * 132 + lm] = a1.w;

        {
            int kk = tid >> 4, ns = (tid & 15) * 8;
            const float* Bp = Bw + (size_t)(k0 + kk) * D + n0 + ns;
            float4 b0 = *(const float4*)Bp;
            float4 b1 = *(const float4*)(Bp + 4);
            *(float4*)&Bs[kk * 132 + ns] = b0;
            *(float4*)&Bs[kk * 132 + ns + 4] = b1;
        }
        __syncthreads();
#pragma unroll
        for (int kk = 0; kk < 16; kk++) {
            const float* ap = &As[kk * 132 + ty * 8];
            const float* bp = &Bs[kk * 132 + tx * 8];
            float4 A0 = *(const float4*)ap, A1 = *(const float4*)(ap + 4);
            float4 B0 = *(const float4*)bp, B1 = *(const float4*)(bp + 4);
            float av[8] = {A0.x, A0.y, A0.z, A0.w, A1.x, A1.y, A1.z, A1.w};
            float bv[8] = {B0.x, B0.y, B0.z, B0.w, B1.x, B1.y, B1.z, B1.w};
#pragma unroll
            for (int i = 0; i < 8; i++)
#pragma unroll
                for (int j = 0; j < 8; j++)
                    acc[i][j] = fmaf(av[i], bv[j], acc[i][j]);
        }
        __syncthreads();
    }

    float bb[8];
#pragma unroll
    for (int j = 0; j < 8; j++) bb[j] = bias[n0 + tx * 8 + j];

    if (EPI == 0) {
        float ps[8], ps2[8];
#pragma unroll
        for (int j = 0; j < 8; j++) { ps[j] = 0.f; ps2[j] = 0.f; }
#pragma unroll
        for (int i = 0; i < 8; i++) {
            float v[8];
#pragma unroll
            for (int j = 0; j < 8; j++) {
                v[j] = acc[i][j] + bb[j];
                ps[j] += v[j];
                ps2[j] += v[j] * v[j];
            }
            float* Cr = Cp + (size_t)(m0 + ty * 8 + i) * D + n0 + tx * 8;
            *(float4*)Cr = make_float4(v[0], v[1], v[2], v[3]);
            *(float4*)(Cr + 4) = make_float4(v[4], v[5], v[6], v[7]);
        }
#pragma unroll
        for (int j = 0; j < 8; j++) {
            atomicAdd(&scol[tx * 8 + j], ps[j]);
            atomicAdd(&scol2[tx * 8 + j], ps2[j]);
        }
        __syncthreads();
        if (tid < 128) {
            atomicAdd(&g_stats[bank * 512 + n0 + tid], scol[tid]);
            atomicAdd(&g_stats[bank * 512 + 256 + n0 + tid], scol2[tid]);
        }
    } else if (EPI == 1) {
        float loc = 0.f;
#pragma unroll
        for (int i = 0; i < 8; i++) {
            const float* er = cmp + (size_t)sidx[ty * 8 + i] * D + n0 + tx * 8;
            float v[8];
#pragma unroll
            for (int j = 0; j < 8; j++) {
                v[j] = acc[i][j] + bb[j];
                float dd = v[j] - er[j];
                loc += dd * dd;
            }
            float* Cr = Cp + (size_t)(m0 + ty * 8 + i) * D + n0 + tx * 8;
            *(float4*)Cr = make_float4(v[0], v[1], v[2], v[3]);
            *(float4*)(Cr + 4) = make_float4(v[4], v[5], v[6], v[7]);
        }
        float r = bred256(loc, red);
        if (tid == 0) atomicAdd(&g_acc[1], (double)r);
    } else {
        float loc = 0.f;
#pragma unroll
        for (int i = 0; i < 8; i++) {
            const float* cr = cmp + (size_t)(m0 + ty * 8 + i) * D + n0 + tx * 8;
#pragma unroll
            for (int j = 0; j < 8; j++) {
                float v = acc[i][j] + bb[j];
                float dd = v - cr[j];
                loc += dd * dd;
            }
        }
        float r = bred256(loc, red);
        if (tid == 0) atomicAdd(&g_acc[2], (double)r);
    }
}

// ------------------------- BN stats -> combined scale/shift -------------------------
__global__ void k_stats(int bank, const float* __restrict__ g,
                        const float* __restrict__ beta, float invB) {
    int t = threadIdx.x;
    float s = g_stats[bank * 512 + t];
    float s2 = g_stats[bank * 512 + 256 + t];
    float mu = s * invB;
    float var = s2 * invB - mu * mu;
    float rs = rsqrtf(var + BNEPS);
    float sc = rs * g[t];
    g_scale[bank * 256 + t] = sc;
    g_shift[bank * 256 + t] = beta[t] - mu * sc;
}

// ------------------------- unique-code (loss_i) path -------------------------
__global__ void k_hU(const float* __restrict__ emb, const float* __restrict__ W1,
                     const float* __restrict__ b1) {
    __shared__ float e[256];
    int k = blockIdx.x, t = threadIdx.x;
    e[t] = emb[k * D + t];
    __syncthreads();
    float acc = 0.f;
#pragma unroll 4
    for (int d = 0; d < D; d++) acc = fmaf(e[d], W1[(size_t)d * D + t], acc);
    g_hU[k * D + t] = acc + b1[t];
}

__global__ void k_statsU(const float* __restrict__ g, const float* __restrict__ beta,
                         float invB) {
    int t = threadIdx.x;
    float s = 0.f, s2 = 0.f;
#pragma unroll 4
    for (int k = 0; k < KC; k++) {
        float c = g_cnt[k];
        float h = g_hU[k * D + t];
        s += c * h;
        s2 += c * h * h;
    }
    float mu = s * invB;
    float var = s2 * invB - mu * mu;
    float rs = rsqrtf(var + BNEPS);
    float sc = rs * g[t];
    g_scaleU[t] = sc;
    g_shiftU[t] = beta[t] - mu * sc;
}

__global__ void k_outU(const float* __restrict__ W2, const float* __restrict__ b2) {
    __shared__ float a[256];
    int k = blockIdx.x, t = threadIdx.x;
    a[t] = fmaxf(0.f, fmaf(g_hU[k * D + t], g_scaleU[t], g_shiftU[t]));
    __syncthreads();
    float acc = 0.f;
#pragma unroll 4
    for (int d = 0; d < D; d++) acc = fmaf(a[d], W2[(size_t)d * D + t], acc);
    g_outU[k * D + t] = acc + b2[t];
}

__global__ void k_lossi(const float* __restrict__ z1) {
    __shared__ float red[256];
    int t = threadIdx.x;
    size_t base = (size_t)blockIdx.x * 2048;
    float loc = 0.f;
#pragma unroll
    for (int s = 0; s < 8; s++) {
        size_t i = base + (size_t)s * 256 + t;
        int row = (int)(i >> 8);
        int c = (int)(i & 255);
        float o = g_outU[g_idx[row] * D + c];
        float dd = z1[i] - o;
        loc += dd * dd;
    }
    float r = bred256(loc, red);
    if (t == 0) atomicAdd(&g_acc[3], (double)r);
}

// ------------------------- final combine -------------------------
__global__ void k_final(float* __restrict__ out, int out_size, int B) {
    __shared__ double dred[1024];
    int t = threadIdx.x;
    double s = 0.0;
    for (int b = t; b < B; b += 1024)
        s += (double)g_bsum[b] / (double)fmaxf(g_bcnt[b], 1.0f);
    dred[t] = s;
    __syncthreads();
#pragma unroll
    for (int st = 512; st > 0; st >>= 1) {
        if (t < st) dred[t] += dred[t + st];
        __syncthreads();
    }
    if (t == 0) {
        double invBD = 1.0 / ((double)B * (double)D);
        double atom = dred[0] / (double)B;
        double vq = 2.0 * g_acc[0] * invBD;
        double lp = g_acc[1] * invBD;
        double lc = g_acc[2] * invBD;
        double li = g_acc[3] * invBD;
        double cyc = lp + li + lc;
        double latt = g_acc[5] / ((double)B * 6.0) * 10.0;
        double loss = cyc + atom + latt + vq;
        float vals[5] = {(float)loss, (float)cyc, (float)atom, (float)latt, (float)vq};
        for (int i = 0; i < out_size; i++) out[i] = (i < 5) ? vals[i] : 0.f;
    }
}

// ------------------------- launch -------------------------
extern "C" void kernel_launch(void* const* d_in, const int* in_sizes, int n_in,
                              void* d_out, int out_size) {
    const float* z1   = (const float*)d_in[0];
    const float* z2   = (const float*)d_in[1];
    const float* zn   = (const float*)d_in[2];
    const float* emb  = (const float*)d_in[3];
    const float* pW1  = (const float*)d_in[4];
    const float* pb1  = (const float*)d_in[5];
    const float* pg   = (const float*)d_in[6];
    const float* pbe  = (const float*)d_in[7];
    const float* pW2  = (const float*)d_in[8];
    const float* pb2  = (const float*)d_in[9];
    const float* iW1  = (const float*)d_in[10];
    const float* ib1  = (const float*)d_in[11];
    const float* ig   = (const float*)d_in[12];
    const float* ibe  = (const float*)d_in[13];
    const float* iW2  = (const float*)d_in[14];
    const float* ib2  = (const float*)d_in[15];
    const float* lw   = (const float*)d_in[16];
    const float* lb   = (const float*)d_in[17];
    const float* aW   = (const float*)d_in[18];
    const float* ab   = (const float*)d_in[19];
    const float* smean = (const float*)d_in[20];
    const float* sstd  = (const float*)d_in[21];
    const float* ls    = (const float*)d_in[22];
    const int* bidx = (const int*)d_in[24];
    const int* anum = (const int*)d_in[25];

    int B = in_sizes[0] / D;    // 32768
    int NA = in_sizes[2] / D;   // 262144
    float invB = 1.0f / (float)B;

    k_init<<<128, 256>>>();
    k_emb_pre<<<KC, 256>>>(emb, lw, lb);

    // VQ (needs embsq/laU) -> idx, cnt, vq sse, latt loss
    k_cgemm<0><<<B / 128, 256>>>(z2, emb, nullptr, nullptr, nullptr, ls, smean, sstd);
    // atom CE (independent)
    k_cgemm<1><<<NA / 128, 256>>>(zn, aW, ab, anum, bidx, nullptr, nullptr, nullptr);

    dim3 gg(2, B / 128);
    // GEMM1: h1 = z1 @ proj_W1 + b1 -> g_h1, stats bank0
    k_dgemm<0, 0><<<gg, 256>>>(z1, 0, pW1, pb1, 1, 0, nullptr);
    k_stats<<<1, 256>>>(0, pg, pbe, invB);
    // GEMM2: p1 = BNrelu(h1) @ proj_W2 + b2 -> g_p1, loss_p vs emb[idx]
    k_dgemm<1, 1><<<gg, 256>>>(nullptr, 1, pW2, pb2, 2, 0, emb);
    // GEMM3: h2 = p1 @ invp_W1 + b1 -> g_h1, stats bank1
    k_dgemm<0, 0><<<gg, 256>>>(nullptr, 2, iW1, ib1, 1, 1, nullptr);
    k_stats<<<1, 256>>>(1, ig, ibe, invB);
    // GEMM4: out = BNrelu(h2) @ invp_W2 + b2, loss_c vs z1 (no store)
    k_dgemm<2, 1><<<gg, 256>>>(nullptr, 1, iW2, ib2, 0, 1, z1);

    // loss_i via unique codes (needs g_cnt, g_idx from VQ)
    k_hU<<<KC, 256>>>(emb, iW1, ib1);
    k_statsU<<<1, 256>>>(ig, ibe, invB);
    k_outU<<<KC, 256>>>(iW2, ib2);
    k_lossi<<<B / 8, 256>>>(z1);

    k_final<<<1, 1024>>>((float*)d_out, out_size, B);
}

// round 5
// speedup vs baseline: 1.7155x; 1.7155x over previous
#include <cuda_runtime.h>
#include <math.h>
#include <stdint.h>

#define D   256
#define KC  100
#define BNEPS 1e-5f
#define LDA 36
#define LDB 136

// ------------------------- device scratch -------------------------
__device__ float  g_h1[32768 * 256];
__device__ float  g_p1[32768 * 256];
__device__ int    g_idx[32768];
__device__ float  g_stats[1024];
__device__ float  g_scale[512], g_shift[512];
__device__ float  g_cnt[KC];
__device__ float  g_embsq[KC];
__device__ float  g_laU[KC * 6];
__device__ float  g_hU[KC * D];
__device__ float  g_outU[KC * D];
__device__ float  g_scaleU[D], g_shiftU[D];
__device__ float  g_bsum[32768];
__device__ float  g_bcnt[32768];
__device__ double g_acc[8];   // 0 vq_sse, 1 loss_p, 2 loss_c, 3 loss_i, 5 latt

// ------------------------- helpers -------------------------
__device__ __forceinline__ uint32_t f2tf(float f) {
    uint32_t u;
    asm("cvt.rna.tf32.f32 %0, %1;" : "=r"(u) : "f"(f));
    return u;
}

__device__ __forceinline__ void mma8(float4& d, const uint32_t* a, const uint32_t* b) {
    asm("mma.sync.aligned.m16n8k8.row.col.f32.tf32.tf32.f32 "
        "{%0,%1,%2,%3}, {%4,%5,%6,%7}, {%8,%9}, {%0,%1,%2,%3};"
        : "+f"(d.x), "+f"(d.y), "+f"(d.z), "+f"(d.w)
        : "r"(a[0]), "r"(a[1]), "r"(a[2]), "r"(a[3]), "r"(b[0]), "r"(b[1]));
}

// block-wide sum -> atomicAdd to double accumulator (all 256 threads must call)
__device__ __forceinline__ void blk_atomic(float v, float* sred, double* dst) {
    int lane = threadIdx.x & 31, w = threadIdx.x >> 5;
#pragma unroll
    for (int o = 16; o; o >>= 1) v += __shfl_down_sync(0xffffffffu, v, o);
    if (lane == 0) sred[w] = v;
    __syncthreads();
    if (threadIdx.x == 0) {
        float s = 0.f;
#pragma unroll
        for (int i = 0; i < 8; i++) s += sred[i];
        atomicAdd(dst, (double)s);
    }
    __syncthreads();
}

// ------------------------- init -------------------------
__global__ void k_init() {
    int i = blockIdx.x * 256 + threadIdx.x;
    g_bsum[i] = 0.f;
    g_bcnt[i] = 0.f;
    if (i < 1024) g_stats[i] = 0.f;
    if (i < KC)   g_cnt[i] = 0.f;
    if (i < 8)    g_acc[i] = 0.0;
}

// ------------------------- per-code precompute -------------------------
__global__ void k_emb_pre(const float* __restrict__ emb, const float* __restrict__ lw,
                          const float* __restrict__ lb) {
    __shared__ float red[256];
    int k = blockIdx.x, t = threadIdx.x;
    float v = emb[k * D + t];
    red[t] = v * v;
    __syncthreads();
#pragma unroll
    for (int s = 128; s > 0; s >>= 1) {
        if (t < s) red[t] += red[t + s];
        __syncthreads();
    }
    if (t == 0) g_embsq[k] = red[0];
    __syncthreads();
#pragma unroll
    for (int j = 0; j < 6; j++) {
        red[t] = v * lw[t * 6 + j];
        __syncthreads();
#pragma unroll
        for (int s = 128; s > 0; s >>= 1) {
            if (t < s) red[t] += red[t + s];
            __syncthreads();
        }
        if (t == 0) g_laU[k * 6 + j] = red[0] + lb[j];
        __syncthreads();
    }
}

// ------------------------- tf32 tensor-core GEMM: VQ / atom CE -------------------------
// MODE 0: VQ on z2 (argmin, counts, vq sse, lattice loss).  Bw = emb [n][k]
// MODE 1: atom logits on zn -> CE.                          Bw = atom_W [k][n], row stride KC
template <int MODE>
__global__ __launch_bounds__(256)
void k_cgemm(const float* __restrict__ A, const float* __restrict__ Bw,
             const float* __restrict__ bias, const int* __restrict__ tgt,
             const int* __restrict__ bidx,
             const float* __restrict__ ls, const float* __restrict__ smean,
             const float* __restrict__ sstd) {
    __shared__ uint32_t As[128 * LDA];
    __shared__ uint32_t Bs[32 * LDB];
    __shared__ float rowsq[256];
    __shared__ float pm1[128 * 4];
    __shared__ float pm2[128 * 4];
    __shared__ float rr[128];
    __shared__ int   stgt[128];
    __shared__ float sred[8];

    const int tid = threadIdx.x;
    const int lane = tid & 31, w = tid >> 5;
    const int g = lane >> 2, tig = lane & 3;
    const int wM = (w >> 2) * 64, wN = (w & 3) * 32;
    const int nw = w & 3;
    const int m0 = blockIdx.x * 128;

    if (MODE == 1 && tid < 128) stgt[tid] = tgt[m0 + tid];

    float4 acc[4][4];
#pragma unroll
    for (int i = 0; i < 4; i++)
#pragma unroll
        for (int j = 0; j < 4; j++) acc[i][j] = make_float4(0.f, 0.f, 0.f, 0.f);
    float asq = 0.f;

    const int arow = tid >> 1, ac0 = (tid & 1) * 16;

    for (int k0 = 0; k0 < D; k0 += 32) {
        __syncthreads();
        // A tile [128][32]
        {
            const float* Ap = A + (size_t)(m0 + arow) * D + k0 + ac0;
#pragma unroll
            for (int q = 0; q < 4; q++) {
                float4 v = *(const float4*)(Ap + q * 4);
                if (MODE == 0)
                    asq += v.x * v.x + v.y * v.y + v.z * v.z + v.w * v.w;
                int c = ac0 + q * 4;
                As[arow * LDA + c + 0] = f2tf(v.x);
                As[arow * LDA + c + 1] = f2tf(v.y);
                As[arow * LDA + c + 2] = f2tf(v.z);
                As[arow * LDA + c + 3] = f2tf(v.w);
            }
        }
        // B tile [32][128] (k-major), padded cols >= KC with 0
        if (MODE == 1) {
            int brow = tid >> 3, bc0 = (tid & 7) * 16;
#pragma unroll
            for (int e = 0; e < 16; e++) {
                int n = bc0 + e;
                float v = (n < KC) ? Bw[(size_t)(k0 + brow) * KC + n] : 0.f;
                Bs[brow * LDB + n] = f2tf(v);
            }
        } else {
            int n = tid >> 1, ks0 = (tid & 1) * 16;
#pragma unroll
            for (int e = 0; e < 16; e++) {
                int kk = ks0 + e;
                float v = (n < KC) ? Bw[(size_t)n * D + k0 + kk] : 0.f;
                Bs[kk * LDB + n] = f2tf(v);
            }
        }
        __syncthreads();
#pragma unroll
        for (int ks = 0; ks < 4; ks++) {
            const int kb = ks * 8;
            uint32_t af[4][4];
#pragma unroll
            for (int mf = 0; mf < 4; mf++) {
                int mb = wM + mf * 16;
                af[mf][0] = As[(mb + g) * LDA + kb + tig];
                af[mf][1] = As[(mb + g + 8) * LDA + kb + tig];
                af[mf][2] = As[(mb + g) * LDA + kb + tig + 4];
                af[mf][3] = As[(mb + g + 8) * LDA + kb + tig + 4];
            }
            uint32_t bf[4][2];
#pragma unroll
            for (int nf = 0; nf < 4; nf++) {
                int n = wN + nf * 8 + g;
                bf[nf][0] = Bs[(kb + tig) * LDB + n];
                bf[nf][1] = Bs[(kb + tig + 4) * LDB + n];
            }
#pragma unroll
            for (int mf = 0; mf < 4; mf++)
#pragma unroll
                for (int nf = 0; nf < 4; nf++)
                    mma8(acc[mf][nf], af[mf], bf[nf]);
        }
    }
    __syncthreads();

    if (MODE == 0) {
        rowsq[arow * 2 + (tid & 1)] = asq;
        float bm[4][2];
        int   ba[4][2];
#pragma unroll
        for (int mf = 0; mf < 4; mf++) { bm[mf][0] = 3.4e38f; bm[mf][1] = 3.4e38f; ba[mf][0] = 0; ba[mf][1] = 0; }
#pragma unroll
        for (int mf = 0; mf < 4; mf++)
#pragma unroll
            for (int nf = 0; nf < 4; nf++) {
                int col0 = wN + nf * 8 + 2 * tig, col1 = col0 + 1;
                float4 c = acc[mf][nf];
                float e0 = (col0 < KC) ? g_embsq[col0] : 3.0e38f;
                float e1 = (col1 < KC) ? g_embsq[col1] : 3.0e38f;
                float d0 = e0 - 2.f * c.x;
                float d1 = e1 - 2.f * c.y;
                float d2 = e0 - 2.f * c.z;
                float d3 = e1 - 2.f * c.w;
                if (col0 >= KC) { d0 = 3.0e38f; d2 = 3.0e38f; }
                if (col1 >= KC) { d1 = 3.0e38f; d3 = 3.0e38f; }
                if (d0 < bm[mf][0]) { bm[mf][0] = d0; ba[mf][0] = col0; }
                if (d1 < bm[mf][0]) { bm[mf][0] = d1; ba[mf][0] = col1; }
                if (d2 < bm[mf][1]) { bm[mf][1] = d2; ba[mf][1] = col0; }
                if (d3 < bm[mf][1]) { bm[mf][1] = d3; ba[mf][1] = col1; }
            }
#pragma unroll
        for (int mf = 0; mf < 4; mf++)
#pragma unroll
            for (int h = 0; h < 2; h++) {
#pragma unroll
                for (int o = 1; o <= 2; o <<= 1) {
                    float ov = __shfl_xor_sync(0xffffffffu, bm[mf][h], o);
                    int   oa = __shfl_xor_sync(0xffffffffu, ba[mf][h], o);
                    if (ov < bm[mf][h]) { bm[mf][h] = ov; ba[mf][h] = oa; }
                }
            }
        if (tig == 0) {
#pragma unroll
            for (int mf = 0; mf < 4; mf++)
#pragma unroll
                for (int h = 0; h < 2; h++) {
                    int row = wM + mf * 16 + g + h * 8;
                    pm1[row * 4 + nw] = bm[mf][h];
                    pm2[row * 4 + nw] = __int_as_float(ba[mf][h]);
                }
        }
        __syncthreads();
        float myloc = 0.f, mylat = 0.f;
        if (tid < 128) {
            float best = 3.4e38f;
            int barg = 0;
#pragma unroll
            for (int q = 0; q < 4; q++) {
                float v = pm1[tid * 4 + q];
                if (v < best) { best = v; barg = __float_as_int(pm2[tid * 4 + q]); }
            }
            int grow = m0 + tid;
            g_idx[grow] = barg;
            atomicAdd(&g_cnt[barg], 1.f);
            myloc = best + rowsq[tid * 2] + rowsq[tid * 2 + 1];
            float lat = 0.f;
#pragma unroll
            for (int j = 0; j < 6; j++) {
                float tv = (ls[(size_t)grow * 6 + j] - smean[j]) / sstd[j];
                float dd = g_laU[barg * 6 + j] - tv;
                lat += dd * dd;
            }
            mylat = lat;
        }
        blk_atomic(myloc, sred, &g_acc[0]);
        blk_atomic(mylat, sred, &g_acc[5]);
    } else {
        float bb0[4], bb1[4];
#pragma unroll
        for (int nf = 0; nf < 4; nf++) {
            int col0 = wN + nf * 8 + 2 * tig, col1 = col0 + 1;
            bb0[nf] = (col0 < KC) ? __ldg(&bias[col0]) : 0.f;
            bb1[nf] = (col1 < KC) ? __ldg(&bias[col1]) : 0.f;
        }
        float mx[4][2];
#pragma unroll
        for (int mf = 0; mf < 4; mf++) { mx[mf][0] = -3.4e38f; mx[mf][1] = -3.4e38f; }
#pragma unroll
        for (int mf = 0; mf < 4; mf++)
#pragma unroll
            for (int nf = 0; nf < 4; nf++) {
                int col0 = wN + nf * 8 + 2 * tig, col1 = col0 + 1;
                float4 c = acc[mf][nf];
                c.x += bb0[nf]; c.y += bb1[nf]; c.z += bb0[nf]; c.w += bb1[nf];
                acc[mf][nf] = c;
                if (col0 < KC) { mx[mf][0] = fmaxf(mx[mf][0], c.x); mx[mf][1] = fmaxf(mx[mf][1], c.z); }
                if (col1 < KC) { mx[mf][0] = fmaxf(mx[mf][0], c.y); mx[mf][1] = fmaxf(mx[mf][1], c.w); }
            }
#pragma unroll
        for (int mf = 0; mf < 4; mf++)
#pragma unroll
            for (int h = 0; h < 2; h++) {
#pragma unroll
                for (int o = 1; o <= 2; o <<= 1)
                    mx[mf][h] = fmaxf(mx[mf][h], __shfl_xor_sync(0xffffffffu, mx[mf][h], o));
            }
        if (tig == 0) {
#pragma unroll
            for (int mf = 0; mf < 4; mf++)
#pragma unroll
                for (int h = 0; h < 2; h++) {
                    int row = wM + mf * 16 + g + h * 8;
                    pm1[row * 4 + nw] = mx[mf][h];
                }
        }
        __syncthreads();
        if (tid < 128) {
            float m = fmaxf(fmaxf(pm1[tid * 4 + 0], pm1[tid * 4 + 1]),
                            fmaxf(pm1[tid * 4 + 2], pm1[tid * 4 + 3]));
            rr[tid] = m;
        }
        __syncthreads();
        float se[4][2], tl[4][2];
#pragma unroll
        for (int mf = 0; mf < 4; mf++) { se[mf][0] = 0.f; se[mf][1] = 0.f; tl[mf][0] = 0.f; tl[mf][1] = 0.f; }
#pragma unroll
        for (int mf = 0; mf < 4; mf++) {
            int r0 = wM + mf * 16 + g, r1 = r0 + 8;
            float m0v = rr[r0], m1v = rr[r1];
            int t0 = stgt[r0], t1 = stgt[r1];
#pragma unroll
            for (int nf = 0; nf < 4; nf++) {
                int col0 = wN + nf * 8 + 2 * tig, col1 = col0 + 1;
                float4 c = acc[mf][nf];
                if (col0 < KC) {
                    se[mf][0] += __expf(c.x - m0v);
                    se[mf][1] += __expf(c.z - m1v);
                    if (col0 == t0) tl[mf][0] = c.x;
                    if (col0 == t1) tl[mf][1] = c.z;
                }
                if (col1 < KC) {
                    se[mf][0] += __expf(c.y - m0v);
                    se[mf][1] += __expf(c.w - m1v);
                    if (col1 == t0) tl[mf][0] = c.y;
                    if (col1 == t1) tl[mf][1] = c.w;
                }
            }
        }
#pragma unroll
        for (int mf = 0; mf < 4; mf++)
#pragma unroll
            for (int h = 0; h < 2; h++) {
#pragma unroll
                for (int o = 1; o <= 2; o <<= 1) {
                    se[mf][h] += __shfl_xor_sync(0xffffffffu, se[mf][h], o);
                    tl[mf][h] += __shfl_xor_sync(0xffffffffu, tl[mf][h], o);
                }
            }
        if (tig == 0) {
#pragma unroll
            for (int mf = 0; mf < 4; mf++)
#pragma unroll
                for (int h = 0; h < 2; h++) {
                    int row = wM + mf * 16 + g + h * 8;
                    pm1[row * 4 + nw] = se[mf][h];
                    pm2[row * 4 + nw] = tl[mf][h];
                }
        }
        __syncthreads();
        if (tid < 128) {
            float S = pm1[tid * 4] + pm1[tid * 4 + 1] + pm1[tid * 4 + 2] + pm1[tid * 4 + 3];
            float T = pm2[tid * 4] + pm2[tid * 4 + 1] + pm2[tid * 4 + 2] + pm2[tid * 4 + 3];
            float ce = rr[tid] + __logf(S) - T;
            int gb = bidx[m0 + tid];
            atomicAdd(&g_bsum[gb], ce);
            atomicAdd(&g_bcnt[gb], 1.f);
        }
    }
}

// ------------------------- tf32 tensor-core D x D MLP GEMM -------------------------
template <int EPI, int BN>
__global__ __launch_bounds__(256)
void k_dgemm(const float* __restrict__ Aext, int aSel,
             const float* __restrict__ Bw, const float* __restrict__ bias,
             int outSel, int bank, const float* __restrict__ cmp) {
    __shared__ uint32_t As[128 * LDA];
    __shared__ uint32_t Bs[32 * LDB];
    __shared__ float sS[256], sH[256];
    __shared__ int   sidx[128];
    __shared__ float sred[8];

    const int tid = threadIdx.x;
    const int lane = tid & 31, w = tid >> 5;
    const int g = lane >> 2, tig = lane & 3;
    const int wM = (w >> 2) * 64, wN = (w & 3) * 32;
    const int m0 = blockIdx.y * 128, n0 = blockIdx.x * 128;

    const float* A = (aSel == 0) ? Aext : ((aSel == 1) ? g_h1 : g_p1);
    float* Cp = (outSel == 1) ? g_h1 : g_p1;

    if (BN) {
        sS[tid] = g_scale[bank * 256 + tid];
        sH[tid] = g_shift[bank * 256 + tid];
    }
    if (EPI == 1 && tid < 128) sidx[tid] = g_idx[m0 + tid];

    float4 acc[4][4];
#pragma unroll
    for (int i = 0; i < 4; i++)
#pragma unroll
        for (int j = 0; j < 4; j++) acc[i][j] = make_float4(0.f, 0.f, 0.f, 0.f);

    const int arow = tid >> 1, ac0 = (tid & 1) * 16;
    const int brow = tid >> 3, bc0 = (tid & 7) * 16;

    for (int k0 = 0; k0 < D; k0 += 32) {
        __syncthreads();
        {
            const float* Ap = A + (size_t)(m0 + arow) * D + k0 + ac0;
#pragma unroll
            for (int q = 0; q < 4; q++) {
                float4 v = *(const float4*)(Ap + q * 4);
                int c = ac0 + q * 4;
                if (BN) {
                    int kc = k0 + c;
                    v.x = fmaxf(0.f, fmaf(v.x, sS[kc + 0], sH[kc + 0]));
                    v.y = fmaxf(0.f, fmaf(v.y, sS[kc + 1], sH[kc + 1]));
                    v.z = fmaxf(0.f, fmaf(v.z, sS[kc + 2], sH[kc + 2]));
                    v.w = fmaxf(0.f, fmaf(v.w, sS[kc + 3], sH[kc + 3]));
                }
                As[arow * LDA + c + 0] = f2tf(v.x);
                As[arow * LDA + c + 1] = f2tf(v.y);
                As[arow * LDA + c + 2] = f2tf(v.z);
                As[arow * LDA + c + 3] = f2tf(v.w);
            }
        }
        {
            const float* Bp = Bw + (size_t)(k0 + brow) * D + n0 + bc0;
#pragma unroll
            for (int q = 0; q < 4; q++) {
                float4 v = *(const float4*)(Bp + q * 4);
                int c = bc0 + q * 4;
                Bs[brow * LDB + c + 0] = f2tf(v.x);
                Bs[brow * LDB + c + 1] = f2tf(v.y);
                Bs[brow * LDB + c + 2] = f2tf(v.z);
                Bs[brow * LDB + c + 3] = f2tf(v.w);
            }
        }
        __syncthreads();
#pragma unroll
        for (int ks = 0; ks < 4; ks++) {
            const int kb = ks * 8;
            uint32_t af[4][4];
#pragma unroll
            for (int mf = 0; mf < 4; mf++) {
                int mb = wM + mf * 16;
                af[mf][0] = As[(mb + g) * LDA + kb + tig];
                af[mf][1] = As[(mb + g + 8) * LDA + kb + tig];
                af[mf][2] = As[(mb + g) * LDA + kb + tig + 4];
                af[mf][3] = As[(mb + g + 8) * LDA + kb + tig + 4];
            }
            uint32_t bf[4][2];
#pragma unroll
            for (int nf = 0; nf < 4; nf++) {
                int n = wN + nf * 8 + g;
                bf[nf][0] = Bs[(kb + tig) * LDB + n];
                bf[nf][1] = Bs[(kb + tig + 4) * LDB + n];
            }
#pragma unroll
            for (int mf = 0; mf < 4; mf++)
#pragma unroll
                for (int nf = 0; nf < 4; nf++)
                    mma8(acc[mf][nf], af[mf], bf[nf]);
        }
    }
    __syncthreads();

    float bb0[4], bb1[4];
#pragma unroll
    for (int nf = 0; nf < 4; nf++) {
        int col = n0 + wN + nf * 8 + 2 * tig;
        bb0[nf] = __ldg(&bias[col]);
        bb1[nf] = __ldg(&bias[col + 1]);
    }

    if (EPI == 0) {
        float ps[4][2], ps2[4][2];
#pragma unroll
        for (int nf = 0; nf < 4; nf++) { ps[nf][0] = ps[nf][1] = 0.f; ps2[nf][0] = ps2[nf][1] = 0.f; }
#pragma unroll
        for (int mf = 0; mf < 4; mf++) {
            int r0 = m0 + wM + mf * 16 + g, r1 = r0 + 8;
#pragma unroll
            for (int nf = 0; nf < 4; nf++) {
                int col = n0 + wN + nf * 8 + 2 * tig;
                float4 c = acc[mf][nf];
                c.x += bb0[nf]; c.y += bb1[nf]; c.z += bb0[nf]; c.w += bb1[nf];
                *(float2*)(Cp + (size_t)r0 * D + col) = make_float2(c.x, c.y);
                *(float2*)(Cp + (size_t)r1 * D + col) = make_float2(c.z, c.w);
                ps[nf][0] += c.x + c.z;          ps[nf][1] += c.y + c.w;
                ps2[nf][0] += c.x * c.x + c.z * c.z;  ps2[nf][1] += c.y * c.y + c.w * c.w;
            }
        }
#pragma unroll
        for (int nf = 0; nf < 4; nf++)
#pragma unroll
            for (int b = 0; b < 2; b++) {
#pragma unroll
                for (int o = 16; o >= 4; o >>= 1) {
                    ps[nf][b] += __shfl_down_sync(0xffffffffu, ps[nf][b], o);
                    ps2[nf][b] += __shfl_down_sync(0xffffffffu, ps2[nf][b], o);
                }
            }
        if (g == 0) {
#pragma unroll
            for (int nf = 0; nf < 4; nf++)
#pragma unroll
                for (int b = 0; b < 2; b++) {
                    int col = n0 + wN + nf * 8 + 2 * tig + b;
                    atomicAdd(&g_stats[bank * 512 + col], ps[nf][b]);
                    atomicAdd(&g_stats[bank * 512 + 256 + col], ps2[nf][b]);
                }
        }
    } else if (EPI == 1) {
        float loc = 0.f;
#pragma unroll
        for (int mf = 0; mf < 4; mf++) {
            int rl0 = wM + mf * 16 + g, rl1 = rl0 + 8;
            int r0 = m0 + rl0, r1 = m0 + rl1;
            const float* e0 = cmp + (size_t)sidx[rl0] * D;
            const float* e1 = cmp + (size_t)sidx[rl1] * D;
#pragma unroll
            for (int nf = 0; nf < 4; nf++) {
                int col = n0 + wN + nf * 8 + 2 * tig;
                float4 c = acc[mf][nf];
                c.x += bb0[nf]; c.y += bb1[nf]; c.z += bb0[nf]; c.w += bb1[nf];
                *(float2*)(Cp + (size_t)r0 * D + col) = make_float2(c.x, c.y);
                *(float2*)(Cp + (size_t)r1 * D + col) = make_float2(c.z, c.w);
                float2 v0 = __ldg((const float2*)(e0 + col));
                float2 v1 = __ldg((const float2*)(e1 + col));
                float d0 = c.x - v0.x, d1 = c.y - v0.y, d2 = c.z - v1.x, d3 = c.w - v1.y;
                loc += d0 * d0 + d1 * d1 + d2 * d2 + d3 * d3;
            }
        }
        blk_atomic(loc, sred, &g_acc[1]);
    } else {
        float loc = 0.f;
#pragma unroll
        for (int mf = 0; mf < 4; mf++) {
            int r0 = m0 + wM + mf * 16 + g, r1 = r0 + 8;
#pragma unroll
            for (int nf = 0; nf < 4; nf++) {
                int col = n0 + wN + nf * 8 + 2 * tig;
                float4 c = acc[mf][nf];
                c.x += bb0[nf]; c.y += bb1[nf]; c.z += bb0[nf]; c.w += bb1[nf];
                float2 v0 = __ldg((const float2*)(cmp + (size_t)r0 * D + col));
                float2 v1 = __ldg((const float2*)(cmp + (size_t)r1 * D + col));
                float d0 = c.x - v0.x, d1 = c.y - v0.y, d2 = c.z - v1.x, d3 = c.w - v1.y;
                loc += d0 * d0 + d1 * d1 + d2 * d2 + d3 * d3;
            }
        }
        blk_atomic(loc, sred, &g_acc[2]);
    }
}

// ------------------------- BN stats -> combined scale/shift -------------------------
__global__ void k_stats(int bank, const float* __restrict__ g,
                        const float* __restrict__ beta, float invB) {
    int t = threadIdx.x;
    float s = g_stats[bank * 512 + t];
    float s2 = g_stats[bank * 512 + 256 + t];
    float mu = s * invB;
    float var = s2 * invB - mu * mu;
    float rs = rsqrtf(var + BNEPS);
    float sc = rs * g[t];
    g_scale[bank * 256 + t] = sc;
    g_shift[bank * 256 + t] = beta[t] - mu * sc;
}

// ------------------------- unique-code (loss_i) path -------------------------
__global__ void k_hU(const float* __restrict__ emb, const float* __restrict__ W1,
                     const float* __restrict__ b1) {
    __shared__ float e[256];
    int k = blockIdx.x, t = threadIdx.x;
    e[t] = emb[k * D + t];
    __syncthreads();
    float acc = 0.f;
#pragma unroll 4
    for (int d = 0; d < D; d++) acc = fmaf(e[d], W1[(size_t)d * D + t], acc);
    g_hU[k * D + t] = acc + b1[t];
}

__global__ void k_statsU(const float* __restrict__ g, const float* __restrict__ beta,
                         float invB) {
    int t = threadIdx.x;
    float s = 0.f, s2 = 0.f;
#pragma unroll 4
    for (int k = 0; k < KC; k++) {
        float c = g_cnt[k];
        float h = g_hU[k * D + t];
        s += c * h;
        s2 += c * h * h;
    }
    float mu = s * invB;
    float var = s2 * invB - mu * mu;
    float rs = rsqrtf(var + BNEPS);
    float sc = rs * g[t];
    g_scaleU[t] = sc;
    g_shiftU[t] = beta[t] - mu * sc;
}

__global__ void k_outU(const float* __restrict__ W2, const float* __restrict__ b2) {
    __shared__ float a[256];
    int k = blockIdx.x, t = threadIdx.x;
    a[t] = fmaxf(0.f, fmaf(g_hU[k * D + t], g_scaleU[t], g_shiftU[t]));
    __syncthreads();
    float acc = 0.f;
#pragma unroll 4
    for (int d = 0; d < D; d++) acc = fmaf(a[d], W2[(size_t)d * D + t], acc);
    g_outU[k * D + t] = acc + b2[t];
}

__global__ void k_lossi(const float* __restrict__ z1) {
    __shared__ float sred[8];
    int t = threadIdx.x;
    size_t base = (size_t)blockIdx.x * 2048;
    float loc = 0.f;
#pragma unroll
    for (int s = 0; s < 8; s++) {
        size_t i = base + (size_t)s * 256 + t;
        int row = (int)(i >> 8);
        int c = (int)(i & 255);
        float o = g_outU[g_idx[row] * D + c];
        float dd = z1[i] - o;
        loc += dd * dd;
    }
    blk_atomic(loc, sred, &g_acc[3]);
}

// ------------------------- final combine -------------------------
__global__ void k_final(float* __restrict__ out, int out_size, int B) {
    __shared__ double dred[1024];
    int t = threadIdx.x;
    double s = 0.0;
    for (int b = t; b < B; b += 1024)
        s += (double)g_bsum[b] / (double)fmaxf(g_bcnt[b], 1.0f);
    dred[t] = s;
    __syncthreads();
#pragma unroll
    for (int st = 512; st > 0; st >>= 1) {
        if (t < st) dred[t] += dred[t + st];
        __syncthreads();
    }
    if (t == 0) {
        double invBD = 1.0 / ((double)B * (double)D);
        double atom = dred[0] / (double)B;
        double vq = 2.0 * g_acc[0] * invBD;
        double lp = g_acc[1] * invBD;
        double lc = g_acc[2] * invBD;
        double li = g_acc[3] * invBD;
        double cyc = lp + li + lc;
        double latt = g_acc[5] / ((double)B * 6.0) * 10.0;
        double loss = cyc + atom + latt + vq;
        float vals[5] = {(float)loss, (float)cyc, (float)atom, (float)latt, (float)vq};
        for (int i = 0; i < out_size; i++) out[i] = (i < 5) ? vals[i] : 0.f;
    }
}

// ------------------------- launch -------------------------
extern "C" void kernel_launch(void* const* d_in, const int* in_sizes, int n_in,
                              void* d_out, int out_size) {
    const float* z1   = (const float*)d_in[0];
    const float* z2   = (const float*)d_in[1];
    const float* zn   = (const float*)d_in[2];
    const float* emb  = (const float*)d_in[3];
    const float* pW1  = (const float*)d_in[4];
    const float* pb1  = (const float*)d_in[5];
    const float* pg   = (const float*)d_in[6];
    const float* pbe  = (const float*)d_in[7];
    const float* pW2  = (const float*)d_in[8];
    const float* pb2  = (const float*)d_in[9];
    const float* iW1  = (const float*)d_in[10];
    const float* ib1  = (const float*)d_in[11];
    const float* ig   = (const float*)d_in[12];
    const float* ibe  = (const float*)d_in[13];
    const float* iW2  = (const float*)d_in[14];
    const float* ib2  = (const float*)d_in[15];
    const float* lw   = (const float*)d_in[16];
    const float* lb   = (const float*)d_in[17];
    const float* aW   = (const float*)d_in[18];
    const float* ab   = (const float*)d_in[19];
    const float* smean = (const float*)d_in[20];
    const float* sstd  = (const float*)d_in[21];
    const float* ls    = (const float*)d_in[22];
    const int* bidx = (const int*)d_in[24];
    const int* anum = (const int*)d_in[25];

    int B = in_sizes[0] / D;    // 32768
    int NA = in_sizes[2] / D;   // 262144
    float invB = 1.0f / (float)B;

    k_init<<<128, 256>>>();
    k_emb_pre<<<KC, 256>>>(emb, lw, lb);

    // VQ -> idx, cnt, vq sse, latt loss
    k_cgemm<0><<<B / 128, 256>>>(z2, emb, nullptr, nullptr, nullptr, ls, smean, sstd);
    // atom CE
    k_cgemm<1><<<NA / 128, 256>>>(zn, aW, ab, anum, bidx, nullptr, nullptr, nullptr);

    dim3 gg(2, B / 128);
    // GEMM1: h1 = z1 @ proj_W1 + b1 -> g_h1, stats bank0
    k_dgemm<0, 0><<<gg, 256>>>(z1, 0, pW1, pb1, 1, 0, nullptr);
    k_stats<<<1, 256>>>(0, pg, pbe, invB);
    // GEMM2: p1 = BNrelu(h1) @ proj_W2 + b2 -> g_p1, loss_p vs emb[idx]
    k_dgemm<1, 1><<<gg, 256>>>(nullptr, 1, pW2, pb2, 2, 0, emb);
    // GEMM3: h2 = p1 @ invp_W1 + b1 -> g_h1, stats bank1
    k_dgemm<0, 0><<<gg, 256>>>(nullptr, 2, iW1, ib1, 1, 1, nullptr);
    k_stats<<<1, 256>>>(1, ig, ibe, invB);
    // GEMM4: out = BNrelu(h2) @ invp_W2 + b2, loss_c vs z1 (no store)
    k_dgemm<2, 1><<<gg, 256>>>(nullptr, 1, iW2, ib2, 0, 1, z1);

    // loss_i via unique codes
    k_hU<<<KC, 256>>>(emb, iW1, ib1);
    k_statsU<<<1, 256>>>(ig, ibe, invB);
    k_outU<<<KC, 256>>>(iW2, ib2);
    k_lossi<<<B / 8, 256>>>(z1);

    k_final<<<1, 1024>>>((float*)d_out, out_size, B);
}